// round 1
// baseline (speedup 1.0000x reference)
#include <cuda_runtime.h>

// DotProductCostVolume: out[b,d,h,w] = (1/C) * sum_c left[b,c,h,w]*right[b,c,h,w-d], 0 if w<d
// B=4, C=32, H=256, W=512, D=64, fp32.

#define Bn 4
#define Cn 32
#define Hn 256
#define Wn 512
#define Dn 64
#define TW 128           // output w-columns per CTA
#define RW 192           // TW + 64 halo columns of right
#define NT 128           // threads per CTA

// Element-granular XOR swizzle: makes lane-stride-8 shared reads conflict-free.
__device__ __forceinline__ int sw(int k) { return k ^ ((k >> 5) & 7); }

__global__ __launch_bounds__(NT, 4)
void cost_volume_kernel(const float* __restrict__ left,
                        const float* __restrict__ right,
                        float* __restrict__ out)
{
    __shared__ float Ls[Cn * TW];   // 16 KB
    __shared__ float Rs[Cn * RW];   // 24 KB

    const int tile = blockIdx.x;    // 0..3
    const int h    = blockIdx.y;    // 0..255
    const int b    = blockIdx.z;    // 0..3
    const int w0   = tile * TW;
    const int tid  = threadIdx.x;

    // ---- Stage left tile: L[c][k], k in [0,TW), global w = w0 + k ----
    const float* lbase = left + ((long)(b * Cn) * Hn + h) * Wn;
    #pragma unroll 8
    for (int idx = tid; idx < Cn * TW; idx += NT) {
        int c = idx >> 7;          // /128
        int k = idx & (TW - 1);
        Ls[c * TW + sw(k)] = lbase[c * Hn * Wn + w0 + k];
    }

    // ---- Stage right tile with halo: R[c][k], global w = w0 - 64 + k, zero for w<0 ----
    const float* rbase = right + ((long)(b * Cn) * Hn + h) * Wn;
    #pragma unroll 8
    for (int idx = tid; idx < Cn * RW; idx += NT) {
        int c  = idx / RW;
        int k  = idx - c * RW;
        int gw = w0 - 64 + k;
        float v = (gw >= 0) ? rbase[c * Hn * Wn + gw] : 0.0f;
        Rs[c * RW + sw(k)] = v;
    }
    __syncthreads();

    // ---- Per-thread 8w x 8d register tile ----
    const int wg = tid & 15;   // w-group: covers w0 + wg*8 .. +7
    const int dg = tid >> 4;   // d-group: covers dg*8 .. +7

    float acc[8][8];
    #pragma unroll
    for (int i = 0; i < 8; i++)
        #pragma unroll
        for (int j = 0; j < 8; j++)
            acc[i][j] = 0.0f;

    // Needed R indices per channel: k = 64 + (8wg+i) - (8dg+j), i,j in [0,8)
    //   -> k in [rb, rb+14] with rb = 8wg - 8dg + 57  (>= 1, <= 177; +14 <= 191 < RW)
    const int rb = 8 * wg - 8 * dg + 57;

    // Swizzled offsets are c-invariant: precompute once.
    int loff[8], roff[15];
    #pragma unroll
    for (int i = 0; i < 8; i++)  loff[i] = sw(wg * 8 + i);
    #pragma unroll
    for (int m = 0; m < 15; m++) roff[m] = sw(rb + m);

    #pragma unroll 4
    for (int c = 0; c < Cn; c++) {
        const float* lr = Ls + c * TW;
        const float* rr = Rs + c * RW;
        float l[8], r[15];
        #pragma unroll
        for (int i = 0; i < 8; i++)  l[i] = lr[loff[i]];
        #pragma unroll
        for (int m = 0; m < 15; m++) r[m] = rr[roff[m]];
        #pragma unroll
        for (int i = 0; i < 8; i++)
            #pragma unroll
            for (int j = 0; j < 8; j++)
                acc[i][j] += l[i] * r[7 + i - j];
    }

    // ---- Epilogue: scale by 1/C, vectorized stores ----
    const float sc = 1.0f / (float)Cn;
    float* ob = out + ((long)(b * Dn) * Hn + h) * Wn + w0 + wg * 8;
    #pragma unroll
    for (int j = 0; j < 8; j++) {
        int d = dg * 8 + j;
        float4 v0 = make_float4(acc[0][j] * sc, acc[1][j] * sc,
                                acc[2][j] * sc, acc[3][j] * sc);
        float4 v1 = make_float4(acc[4][j] * sc, acc[5][j] * sc,
                                acc[6][j] * sc, acc[7][j] * sc);
        float4* p = reinterpret_cast<float4*>(ob + (long)d * Hn * Wn);
        p[0] = v0;
        p[1] = v1;
    }
}

extern "C" void kernel_launch(void* const* d_in, const int* in_sizes, int n_in,
                              void* d_out, int out_size)
{
    const float* left  = (const float*)d_in[0];
    const float* right = (const float*)d_in[1];
    float* out = (float*)d_out;

    dim3 grid(Wn / TW, Hn, Bn);   // (4, 256, 4) = 4096 CTAs
    cost_volume_kernel<<<grid, NT>>>(left, right, out);
}